// round 12
// baseline (speedup 1.0000x reference)
#include <cuda_runtime.h>
#include <math.h>

#define NATOM 4096
#define NMET  1024
#define NKH   4630           // half k-space: (21^3 - 1)/2
#define KPAD  9280           // 2*NKH padded to multiple of 16
#define NTILE 136            // 16*17/2 lower-tri 64x64 tiles
#define NB    64
#define NPAN  16
#define NBB   116            // k_B partial blocks (116*80 = 9280)
#define ROWS_C 120           // max trsm rows per cluster rank (960/8)
#define TWO_PI_D 6.283185307179586
#define INV_2PI_D 0.15915494309189535
#define TWO_PI_F 6.2831853f
#define INV_2PI_F 0.15915494f

// ------------------------- device scratch (static) -------------------------
__device__ float  d_sqw[NKH];
__device__ float4 d_uvw[NATOM];
__device__ float  d_PHI[(size_t)KPAD * NMET];
__device__ float  d_sfw[KPAD];
__device__ float  d_A[NMET * NMET];      // A -> L (lower) after chol
__device__ float  d_Afull[NMET * NMET];  // pristine A for refinement
__device__ float  d_LT[NMET * NMET];     // L^T copy (coalesced solves)
__device__ float  d_invf[NMET];          // fp32 reciprocal diag of L
__device__ double d_Bp[NBB][NMET];       // k_B partials
__device__ double d_B[NMET];
__device__ double d_x1[NMET], d_x2[NMET];
__device__ double d_r1[NMET], d_r2[NMET];
__device__ double d_lam;

// 2*pi*inv(cell)^T computed per-thread
static __device__ __forceinline__ void recip_rows(const float* cell, double rcp[9],
                                                  double* wfac) {
    double c[9];
#pragma unroll
    for (int i = 0; i < 9; i++) c[i] = (double)cell[i];
    double det = c[0]*(c[4]*c[8]-c[5]*c[7]) - c[1]*(c[3]*c[8]-c[5]*c[6])
               + c[2]*(c[3]*c[7]-c[4]*c[6]);
    double inv[9];
    inv[0]=(c[4]*c[8]-c[5]*c[7])/det;
    inv[1]=(c[2]*c[7]-c[1]*c[8])/det;
    inv[2]=(c[1]*c[5]-c[2]*c[4])/det;
    inv[3]=(c[5]*c[6]-c[3]*c[8])/det;
    inv[4]=(c[0]*c[8]-c[2]*c[6])/det;
    inv[5]=(c[2]*c[3]-c[0]*c[5])/det;
    inv[6]=(c[3]*c[7]-c[4]*c[6])/det;
    inv[7]=(c[1]*c[6]-c[0]*c[7])/det;
    inv[8]=(c[0]*c[4]-c[1]*c[3])/det;
#pragma unroll
    for (int m = 0; m < 3; m++)
#pragma unroll
        for (int d = 0; d < 3; d++)
            rcp[m*3+d] = TWO_PI_D * inv[d*3+m];
    *wfac = 8.0 * 3.14159265358979323846 / fabs(det);
}

// ------ launch 1: k-weights + per-atom reduced phases + pad zeroing ---------
__global__ void k_prep(const float* __restrict__ pos, const float* __restrict__ cell) {
    int idx = blockIdx.x * blockDim.x + threadIdx.x;
    if (idx < NKH) {
        double rcp[9], wfac;
        recip_rows(cell, rcp, &wfac);
        int a = idx / 441, r = idx % 441, b = r / 21, cc = r % 21;
        double na = a - 10, nb = b - 10, nc = cc - 10;
        double kx = na*rcp[0] + nb*rcp[3] + nc*rcp[6];
        double ky = na*rcp[1] + nb*rcp[4] + nc*rcp[7];
        double kz = na*rcp[2] + nb*rcp[5] + nc*rcp[8];
        double k2 = kx*kx + ky*ky + kz*kz;
        const double SG = 1.0 / 1.805132;
        double kfac = exp(-0.5 * SG * SG * k2) / k2;
        d_sqw[idx] = (float)sqrt(wfac * kfac);
    }
    if (idx < NATOM) {
        double rcp[9], wfac;
        recip_rows(cell, rcp, &wfac);
        double x = pos[3*idx], y = pos[3*idx+1], z = pos[3*idx+2];
        double u = rcp[0]*x + rcp[1]*y + rcp[2]*z;
        double v = rcp[3]*x + rcp[4]*y + rcp[5]*z;
        double w = rcp[6]*x + rcp[7]*y + rcp[8]*z;
        float4 o;
        o.x = (float)(u - TWO_PI_D * rint(u * INV_2PI_D));
        o.y = (float)(v - TWO_PI_D * rint(v * INV_2PI_D));
        o.z = (float)(w - TWO_PI_D * rint(w * INV_2PI_D));
        o.w = 0.f;
        d_uvw[idx] = o;
    }
    if (idx < (KPAD - 2*NKH) * NMET) d_PHI[(size_t)2*NKH*NMET + idx] = 0.f;
    if (idx < KPAD - 2*NKH) d_sfw[2*NKH + idx] = 0.f;
}

// ---------------- launch 2: Phi build (metal atoms) -------------------------
__global__ void k_phi() {
    int t = blockIdx.x;
    int a = t / 441, r = t % 441, b = r / 21, cc = r % 21;
    float na = (float)(a - 10), nb = (float)(b - 10), nc = (float)(cc - 10);
    float sw = d_sqw[t];
    for (int i = threadIdx.x; i < NMET; i += 256) {
        float4 uv = d_uvw[i];
        float ph = na*uv.x + nb*uv.y + nc*uv.z;
        ph -= TWO_PI_F * rintf(ph * INV_2PI_F);
        float s, c;
        __sincosf(ph, &s, &c);
        d_PHI[(size_t)t*NMET + i]         = sw * c;
        d_PHI[(size_t)(NKH + t)*NMET + i] = sw * s;
    }
}

// tri decode: L -> (bi, bj) with bi >= bj
static __device__ __forceinline__ void tri_decode(int L, int* bi, int* bj) {
    int bt = (int)((sqrtf(8.f*L + 1.f) - 1.f) * 0.5f);
    while ((bt+1)*(bt+2)/2 <= L) bt++;
    while (bt*(bt+1)/2 > L) bt--;
    *bi = bt;
    *bj = L - bt*(bt+1)/2;
}

// ------ launch 3: A = PHI^T PHI lower-tri, single-K, direct write -----------
__global__ __launch_bounds__(256) void k_gemm() {
    __shared__ float As[2][16][64];
    __shared__ float Bs[2][16][64];
    int bi, bj;
    tri_decode(blockIdx.x, &bi, &bj);
    bi *= 64; bj *= 64;
    int tid = threadIdx.x;
    int lr = tid >> 4, lc = (tid & 15) * 4;

    *(float4*)&As[0][lr][lc] = *(const float4*)&d_PHI[(size_t)lr*NMET + bi + lc];
    *(float4*)&Bs[0][lr][lc] = *(const float4*)&d_PHI[(size_t)lr*NMET + bj + lc];
    __syncthreads();

    int ty = tid >> 4, tx = tid & 15;
    float acc[4][4] = {};
    int buf = 0;
    for (int t0 = 0; t0 < KPAD; t0 += 16) {
        float4 fa, fb;
        bool more = (t0 + 16 < KPAD);
        if (more) {
            fa = *(const float4*)&d_PHI[(size_t)(t0+16+lr)*NMET + bi + lc];
            fb = *(const float4*)&d_PHI[(size_t)(t0+16+lr)*NMET + bj + lc];
        }
#pragma unroll
        for (int kk = 0; kk < 16; kk++) {
            float4 a4 = *(const float4*)&As[buf][kk][ty*4];
            float4 b4 = *(const float4*)&Bs[buf][kk][tx*4];
            float a[4] = {a4.x, a4.y, a4.z, a4.w};
            float b[4] = {b4.x, b4.y, b4.z, b4.w};
#pragma unroll
            for (int u = 0; u < 4; u++)
#pragma unroll
                for (int v = 0; v < 4; v++) acc[u][v] += a[u] * b[v];
        }
        if (more) {
            __syncthreads();
            *(float4*)&As[buf^1][lr][lc] = fa;
            *(float4*)&Bs[buf^1][lr][lc] = fb;
            __syncthreads();
            buf ^= 1;
        }
    }
#pragma unroll
    for (int u = 0; u < 4; u++)
#pragma unroll
        for (int v = 0; v < 4; v++) {
            int row = bi + ty*4 + u, col = bj + tx*4 + v;
            float vv = acc[u][v];
            d_A[row*NMET + col] = vv;
            d_Afull[row*NMET + col] = vv;
            if (bi != bj) {
                d_A[col*NMET + row] = vv;
                d_Afull[col*NMET + row] = vv;
            }
        }
}

// ---------------- cluster-wide sync (global mem visible) --------------------
static __device__ __forceinline__ void csync() {
    __threadfence();
    asm volatile("barrier.cluster.arrive.aligned;" ::: "memory");
    asm volatile("barrier.cluster.wait.aligned;" ::: "memory");
    __threadfence();
}

// factor 64x64 lower block in smem (stride 65); write L + L^T + inv diag
__device__ void potf_smem(float* sm, float* pinv, int o) {
    int tid = threadIdx.x;
    for (int j = 0; j < 64; j++) {
        if (tid == 0) {
            float s = sqrtf(sm[j*65+j]);
            sm[j*65+j] = s;
            *pinv = 1.0f / s;
        }
        __syncthreads();
        float inv = *pinv;
        for (int i2 = j + 1 + tid; i2 < 64; i2 += 256) sm[i2*65+j] *= inv;
        __syncthreads();
        for (int l = tid; l < 4096; l += 256) {
            int r = l >> 6, c = l & 63;
            if (r > j && c > j && c <= r) sm[r*65+c] -= sm[r*65+j] * sm[c*65+j];
        }
        __syncthreads();
    }
    for (int l = tid; l < 4096; l += 256) {
        int r = l >> 6, c = l & 63;
        float v = (c <= r) ? sm[r*65+c] : 0.0f;
        d_A[(o+r)*NMET + o + c] = v;
        d_LT[(o+c)*NMET + o + r] = v;
    }
    if (tid < 64) d_invf[o+tid] = 1.0f / sm[tid*65+tid];
    __syncthreads();
}

// global float4 load -> scalar smem scatter (smem stride 65 not 16B aligned)
static __device__ __forceinline__ void ld_tile64(float* sm, const float* g, int ldg) {
    int tid = threadIdx.x;
    for (int l = tid; l < 1024; l += 256) {
        int r = l >> 4, c4 = (l & 15) * 4;
        float4 f = *(const float4*)&g[r*ldg + c4];
        sm[r*65 + c4 + 0] = f.x;
        sm[r*65 + c4 + 1] = f.y;
        sm[r*65 + c4 + 2] = f.z;
        sm[r*65 + c4 + 3] = f.w;
    }
}

// ------ launch 4 (ncu-captured): full Cholesky, 8-CTA cluster ---------------
__global__ __launch_bounds__(256) __cluster_dims__(8, 1, 1) void k_chol() {
    __shared__ float pool[4160 + ROWS_C * 65];
    __shared__ float sDi[64];
    __shared__ float sInv;
    float* sA = pool;
    float* sB = pool + 4160;
    int tid = threadIdx.x;
    int rank = blockIdx.x;           // grid == one cluster of 8

    if (rank == 0) {                 // potf panel 0
        ld_tile64(sA, &d_A[0], NMET);
        __syncthreads();
        potf_smem(sA, &sInv, 0);
    }
    csync();

    for (int p = 0; p < NPAN - 1; p++) {
        int o = p * NB, s = o + NB;
        int m = NMET - s;

        // ---- trsm: rows split across 8 ranks -------------------------------
        int chunk = (m + 7) / 8;     // <= ROWS_C
        int r0 = rank * chunk;
        if (r0 < m) {
            int nrows = m - r0; if (nrows > chunk) nrows = chunk;
            ld_tile64(sA, &d_A[o*NMET + o], NMET);
            for (int l = tid; l < nrows * 16; l += 256) {
                int r = l >> 4, c4 = (l & 15) * 4;
                float4 f = *(const float4*)&d_A[(s + r0 + r)*NMET + o + c4];
                sB[r*65 + c4 + 0] = f.x;
                sB[r*65 + c4 + 1] = f.y;
                sB[r*65 + c4 + 2] = f.z;
                sB[r*65 + c4 + 3] = f.w;
            }
            __syncthreads();
            if (tid < 64) sDi[tid] = 1.0f / sA[tid*65+tid];
            __syncthreads();
            if (tid < nrows) {
                float* P = &sB[tid*65];
#pragma unroll 1
                for (int j = 0; j < 64; j++) {
                    float v = P[j];
                    for (int mm = 0; mm < j; mm++) v -= P[mm] * sA[j*65+mm];
                    P[j] = v * sDi[j];
                }
            }
            __syncthreads();
            for (int l = tid; l < nrows * 64; l += 256) {
                int r = l >> 6, c = l & 63;
                d_A[(s + r0 + r)*NMET + o + c] = sB[r*65 + c];
            }
            for (int l = tid; l < nrows * 64; l += 256) {
                int c = l / nrows, r = l % nrows;
                d_LT[(o + c)*NMET + s + r0 + r] = sB[r*65 + c];
            }
        }
        csync();

        // ---- syrk trailing; rank0's tile 0 fuses potf(p+1) -----------------
        int nt = m / NB;
        int ntiles = nt * (nt + 1) / 2;
        for (int idx = rank; idx < ntiles; idx += 8) {
            int I, J;
            tri_decode(idx, &I, &J);
            int rI = s + I*NB, rJ = s + J*NB;
            ld_tile64(sA, &d_A[rI*NMET + o], NMET);
            ld_tile64(sB, &d_A[rJ*NMET + o], NMET);
            __syncthreads();
            int ty = tid >> 4, tx = tid & 15;
            float acc[4][4] = {};
#pragma unroll
            for (int k = 0; k < 64; k++) {
                float a[4], b[4];
#pragma unroll
                for (int u = 0; u < 4; u++) {
                    a[u] = sA[(ty*4+u)*65 + k];
                    b[u] = sB[(tx*4+u)*65 + k];
                }
#pragma unroll
                for (int u = 0; u < 4; u++)
#pragma unroll
                    for (int v = 0; v < 4; v++) acc[u][v] += a[u] * b[v];
            }
            __syncthreads();
            if (idx == 0) {          // next diag tile: update in smem + factor
#pragma unroll
                for (int u = 0; u < 4; u++)
#pragma unroll
                    for (int v = 0; v < 4; v++)
                        sA[(ty*4+u)*65 + tx*4+v] =
                            d_A[(rI+ty*4+u)*NMET + rJ + tx*4+v] - acc[u][v];
                __syncthreads();
                potf_smem(sA, &sInv, rI);
            } else {
#pragma unroll
                for (int u = 0; u < 4; u++)
#pragma unroll
                    for (int v = 0; v < 4; v++)
                        d_A[(rI+ty*4+u)*NMET + rJ + tx*4+v] -= acc[u][v];
                __syncthreads();
            }
        }
        csync();
    }
}

// ---------------- launch 5: structure factors (water) -----------------------
__global__ void k_sf(const float* __restrict__ q) {
    __shared__ float wc[8], ws[8];
    int t = blockIdx.x;
    int a = t / 441, r = t % 441, b = r / 21, cc = r % 21;
    float na = (float)(a - 10), nb = (float)(b - 10), nc = (float)(cc - 10);
    float ac = 0.f, as = 0.f;
    for (int j = NMET + threadIdx.x; j < NATOM; j += 256) {
        float4 uv = d_uvw[j];
        float ph = na*uv.x + nb*uv.y + nc*uv.z;
        ph -= TWO_PI_F * rintf(ph * INV_2PI_F);
        float s, c;
        __sincosf(ph, &s, &c);
        float qq = q[j];
        ac += qq * c;
        as += qq * s;
    }
#pragma unroll
    for (int off = 16; off > 0; off >>= 1) {
        ac += __shfl_down_sync(0xffffffff, ac, off);
        as += __shfl_down_sync(0xffffffff, as, off);
    }
    int lane = threadIdx.x & 31, w = threadIdx.x >> 5;
    if (lane == 0) { wc[w] = ac; ws[w] = as; }
    __syncthreads();
    if (threadIdx.x == 0) {
        float sc = 0.f, ss = 0.f;
#pragma unroll
        for (int u = 0; u < 8; u++) { sc += wc[u]; ss += ws[u]; }
        float sw = d_sqw[t];
        d_sfw[t]       = sw * sc;
        d_sfw[NKH + t] = sw * ss;
    }
}

// ------- launch 6: B partials = PHI^T sfw (116 blocks x 80 k-rows) ----------
__global__ void k_B() {
    int b = blockIdx.x;
    int t0 = b * 80, t1 = t0 + 80;
    int i0 = threadIdx.x;            // atoms i0, i0+256, i0+512, i0+768
    double acc[4] = {0.0, 0.0, 0.0, 0.0};
    for (int t = t0; t < t1; t += 2) {
        float w0 = d_sfw[t], w1 = d_sfw[t+1];
        const float* r0 = &d_PHI[(size_t)t*NMET];
        const float* r1 = r0 + NMET;
#pragma unroll
        for (int u = 0; u < 4; u++) {
            acc[u] += (double)r0[i0 + u*256] * (double)w0
                    + (double)r1[i0 + u*256] * (double)w1;
        }
    }
#pragma unroll
    for (int u = 0; u < 4; u++) d_Bp[b][i0 + u*256] = acc[u];
}

// ------- dual-RHS fp32 triangular solves (refine uses fp64 residual) --------
// refine==0: reduce d_Bp -> d_B, solve;  refine==1: solve residual + output
__global__ __launch_bounds__(1024) void k_trsv(int refine,
                                               const float* __restrict__ q,
                                               float* __restrict__ out) {
    __shared__ float y1[NMET], y2[NMET];
    __shared__ double z1[NMET], z2[NMET];
    __shared__ double lam_s;
    int i = threadIdx.x, lane = i & 31, warp = i >> 5;
    if (refine) {
        y1[i] = (float)d_r1[i]; y2[i] = (float)d_r2[i];
    } else {
        double s = 0.0;
        for (int k = 0; k < NBB; k++) s += d_Bp[k][i];
        double bv = -s;
        d_B[i] = bv;
        y1[i] = (float)bv; y2[i] = 1.0f;
    }
    __syncthreads();

    // forward: L y = b
    for (int jb = 0; jb < NMET; jb += 32) {
        if (warp == 0) {
            float a1 = y1[jb+lane], a2 = y2[jb+lane];
            float di = d_invf[jb+lane];
            float Lr[32];
#pragma unroll
            for (int j4 = 0; j4 < 8; j4++) {
                float4 f = *(const float4*)&d_A[(jb+lane)*NMET + jb + j4*4];
                Lr[j4*4] = f.x; Lr[j4*4+1] = f.y; Lr[j4*4+2] = f.z; Lr[j4*4+3] = f.w;
            }
#pragma unroll
            for (int j = 0; j < 32; j++) {
                float sv = __shfl_sync(0xffffffff, di, j);
                float v1 = __shfl_sync(0xffffffff, a1, j) * sv;
                float v2 = __shfl_sync(0xffffffff, a2, j) * sv;
                if (lane == j) { a1 = v1; a2 = v2; }
                else if (lane > j) {
                    a1 -= Lr[j] * v1; a2 -= Lr[j] * v2;
                }
            }
            y1[jb+lane] = a1; y2[jb+lane] = a2;
        }
        __syncthreads();
        if (i >= jb + 32) {
            float s1 = y1[i], s2 = y2[i];
#pragma unroll
            for (int j = 0; j < 32; j++) {
                float l = d_LT[(jb+j)*NMET + i];
                s1 -= l * y1[jb+j];
                s2 -= l * y2[jb+j];
            }
            y1[i] = s1; y2[i] = s2;
        }
        __syncthreads();
    }

    // backward: L^T x = y
    for (int jb = NMET - 32; jb >= 0; jb -= 32) {
        if (warp == 0) {
            float a1 = y1[jb+lane], a2 = y2[jb+lane];
            float di = d_invf[jb+lane];
            float Lr[32];     // Lr[j] = L^T[jb+lane][jb+j] = L[jb+j][jb+lane]
#pragma unroll
            for (int j4 = 0; j4 < 8; j4++) {
                float4 f = *(const float4*)&d_LT[(jb+lane)*NMET + jb + j4*4];
                Lr[j4*4] = f.x; Lr[j4*4+1] = f.y; Lr[j4*4+2] = f.z; Lr[j4*4+3] = f.w;
            }
#pragma unroll
            for (int j = 31; j >= 0; j--) {
                float sv = __shfl_sync(0xffffffff, di, j);
                float v1 = __shfl_sync(0xffffffff, a1, j) * sv;
                float v2 = __shfl_sync(0xffffffff, a2, j) * sv;
                if (lane == j) { a1 = v1; a2 = v2; }
                else if (lane < j) {
                    a1 -= Lr[j] * v1; a2 -= Lr[j] * v2;
                }
            }
            y1[jb+lane] = a1; y2[jb+lane] = a2;
        }
        __syncthreads();
        if (i < jb) {
            float s1 = y1[i], s2 = y2[i];
#pragma unroll
            for (int j = 0; j < 32; j++) {
                float l = d_A[(jb+j)*NMET + i];   // L rows: coalesced
                s1 -= l * y1[jb+j];
                s2 -= l * y2[jb+j];
            }
            y1[i] = s1; y2[i] = s2;
        }
        __syncthreads();
    }

    double xf1, xf2;
    if (refine) { xf1 = d_x1[i] + (double)y1[i]; xf2 = d_x2[i] + (double)y2[i]; }
    else        { xf1 = (double)y1[i];           xf2 = (double)y2[i]; }
    d_x1[i] = xf1; d_x2[i] = xf2;
    z1[i] = xf1; z2[i] = xf2;
    __syncthreads();
    for (int off = 512; off > 0; off >>= 1) {
        if (i < off) { z1[i] += z1[i+off]; z2[i] += z2[i+off]; }
        __syncthreads();
    }
    if (i == 0) { lam_s = z1[0] / z2[0]; d_lam = lam_s; }
    __syncthreads();
    if (refine) {                    // fused output
        double lam = lam_s;
        out[i] = (float)(xf1 - lam * xf2);
        for (int j = NMET + i; j < NATOM; j += NMET) out[j] = q[j];
    }
}

// ---------------- residual r = b - A x (fp64 accumulate) --------------------
__global__ void k_resid() {
    int lane = threadIdx.x & 31, wr = threadIdx.x >> 5;
    int row = blockIdx.x * 8 + wr;
    double a1 = 0.0, a2 = 0.0;
    for (int j = lane; j < NMET; j += 32) {
        double a = (double)d_Afull[row*NMET + j];
        a1 += a * d_x1[j];
        a2 += a * d_x2[j];
    }
    for (int off = 16; off > 0; off >>= 1) {
        a1 += __shfl_down_sync(0xffffffff, a1, off);
        a2 += __shfl_down_sync(0xffffffff, a2, off);
    }
    if (lane == 0) {
        d_r1[row] = d_B[row] - a1;
        d_r2[row] = 1.0 - a2;
    }
}

// ------------------------------ launch --------------------------------------
extern "C" void kernel_launch(void* const* d_in, const int* in_sizes, int n_in,
                              void* d_out, int out_size) {
    const float* pos  = (const float*)d_in[0];
    const float* q    = (const float*)d_in[1];
    const float* cell = (const float*)d_in[2];
    float* out = (float*)d_out;

    k_prep<<<80, 256>>>(pos, cell);            // 1
    k_phi<<<NKH, 256>>>();                     // 2
    k_gemm<<<NTILE, 256>>>();                  // 3
    k_chol<<<8, 256>>>();                      // 4  <- ncu captures this (cluster)
    k_sf<<<NKH, 256>>>(q);                     // 5
    k_B<<<NBB, 256>>>();                       // 6
    k_trsv<<<1, 1024>>>(0, q, out);            // 7
    k_resid<<<128, 256>>>();                   // 8
    k_trsv<<<1, 1024>>>(1, q, out);            // 9
}

// round 13
// speedup vs baseline: 1.2718x; 1.2718x over previous
#include <cuda_runtime.h>
#include <math.h>

#define NATOM 4096
#define NMET  1024
#define NKH   4630           // half k-space: (21^3 - 1)/2
#define KPAD  9280           // 2*NKH padded to multiple of 16
#define KHALF (KPAD/2)       // split-K halves
#define NTILE 136            // 16*17/2 lower-tri 64x64 tiles
#define NB    64
#define NPAN  16
#define NBB   116            // k_B partial blocks (116*80 = 9280)
#define ROWS_T 96            // trsm panel rows staged in smem
#define TWO_PI_D 6.283185307179586
#define INV_2PI_D 0.15915494309189535
#define TWO_PI_F 6.2831853f
#define INV_2PI_F 0.15915494f

// ------------------------- device scratch (static) -------------------------
__device__ float  d_sqw[NKH];
__device__ float4 d_uvw[NATOM];
__device__ float  d_PHI[(size_t)KPAD * NMET];
__device__ float  d_sfw[KPAD];
__device__ float  d_Ap[2][(size_t)NTILE * 4096];   // split-K partials
__device__ float  d_A[NMET * NMET];      // A -> L (lower) after chol
__device__ float  d_Afull[NMET * NMET];  // pristine A for refinement
__device__ float  d_LT[NMET * NMET];     // L^T copy (coalesced solves)
__device__ float  d_invf[NMET];          // fp32 reciprocal diag of L
__device__ double d_Bp[NBB][NMET];       // k_B partials
__device__ double d_B[NMET];
__device__ double d_x1[NMET], d_x2[NMET];
__device__ double d_r1[NMET], d_r2[NMET];
__device__ double d_lam;

// 2*pi*inv(cell)^T computed per-thread
static __device__ __forceinline__ void recip_rows(const float* cell, double rcp[9],
                                                  double* wfac) {
    double c[9];
#pragma unroll
    for (int i = 0; i < 9; i++) c[i] = (double)cell[i];
    double det = c[0]*(c[4]*c[8]-c[5]*c[7]) - c[1]*(c[3]*c[8]-c[5]*c[6])
               + c[2]*(c[3]*c[7]-c[4]*c[6]);
    double inv[9];
    inv[0]=(c[4]*c[8]-c[5]*c[7])/det;
    inv[1]=(c[2]*c[7]-c[1]*c[8])/det;
    inv[2]=(c[1]*c[5]-c[2]*c[4])/det;
    inv[3]=(c[5]*c[6]-c[3]*c[8])/det;
    inv[4]=(c[0]*c[8]-c[2]*c[6])/det;
    inv[5]=(c[2]*c[3]-c[0]*c[5])/det;
    inv[6]=(c[3]*c[7]-c[4]*c[6])/det;
    inv[7]=(c[1]*c[6]-c[0]*c[7])/det;
    inv[8]=(c[0]*c[4]-c[1]*c[3])/det;
#pragma unroll
    for (int m = 0; m < 3; m++)
#pragma unroll
        for (int d = 0; d < 3; d++)
            rcp[m*3+d] = TWO_PI_D * inv[d*3+m];
    *wfac = 8.0 * 3.14159265358979323846 / fabs(det);
}

// ------ launch 1: k-weights + per-atom reduced phases + pad zeroing ---------
__global__ void k_prep(const float* __restrict__ pos, const float* __restrict__ cell) {
    int idx = blockIdx.x * blockDim.x + threadIdx.x;
    if (idx < NKH) {
        double rcp[9], wfac;
        recip_rows(cell, rcp, &wfac);
        int a = idx / 441, r = idx % 441, b = r / 21, cc = r % 21;
        double na = a - 10, nb = b - 10, nc = cc - 10;
        double kx = na*rcp[0] + nb*rcp[3] + nc*rcp[6];
        double ky = na*rcp[1] + nb*rcp[4] + nc*rcp[7];
        double kz = na*rcp[2] + nb*rcp[5] + nc*rcp[8];
        double k2 = kx*kx + ky*ky + kz*kz;
        const double SG = 1.0 / 1.805132;
        double kfac = exp(-0.5 * SG * SG * k2) / k2;
        d_sqw[idx] = (float)sqrt(wfac * kfac);
    }
    if (idx < NATOM) {
        double rcp[9], wfac;
        recip_rows(cell, rcp, &wfac);
        double x = pos[3*idx], y = pos[3*idx+1], z = pos[3*idx+2];
        double u = rcp[0]*x + rcp[1]*y + rcp[2]*z;
        double v = rcp[3]*x + rcp[4]*y + rcp[5]*z;
        double w = rcp[6]*x + rcp[7]*y + rcp[8]*z;
        float4 o;
        o.x = (float)(u - TWO_PI_D * rint(u * INV_2PI_D));
        o.y = (float)(v - TWO_PI_D * rint(v * INV_2PI_D));
        o.z = (float)(w - TWO_PI_D * rint(w * INV_2PI_D));
        o.w = 0.f;
        d_uvw[idx] = o;
    }
    if (idx < (KPAD - 2*NKH) * NMET) d_PHI[(size_t)2*NKH*NMET + idx] = 0.f;
    if (idx < KPAD - 2*NKH) d_sfw[2*NKH + idx] = 0.f;
}

// ---------------- launch 2: Phi build (metal atoms) -------------------------
__global__ void k_phi() {
    int t = blockIdx.x;
    int a = t / 441, r = t % 441, b = r / 21, cc = r % 21;
    float na = (float)(a - 10), nb = (float)(b - 10), nc = (float)(cc - 10);
    float sw = d_sqw[t];
    for (int i = threadIdx.x; i < NMET; i += 256) {
        float4 uv = d_uvw[i];
        float ph = na*uv.x + nb*uv.y + nc*uv.z;
        ph -= TWO_PI_F * rintf(ph * INV_2PI_F);
        float s, c;
        __sincosf(ph, &s, &c);
        d_PHI[(size_t)t*NMET + i]         = sw * c;
        d_PHI[(size_t)(NKH + t)*NMET + i] = sw * s;
    }
}

// ---------------- launch 3: structure factors (water) -----------------------
__global__ void k_sf(const float* __restrict__ q) {
    __shared__ float wc[8], ws[8];
    int t = blockIdx.x;
    int a = t / 441, r = t % 441, b = r / 21, cc = r % 21;
    float na = (float)(a - 10), nb = (float)(b - 10), nc = (float)(cc - 10);
    float ac = 0.f, as = 0.f;
    for (int j = NMET + threadIdx.x; j < NATOM; j += 256) {
        float4 uv = d_uvw[j];
        float ph = na*uv.x + nb*uv.y + nc*uv.z;
        ph -= TWO_PI_F * rintf(ph * INV_2PI_F);
        float s, c;
        __sincosf(ph, &s, &c);
        float qq = q[j];
        ac += qq * c;
        as += qq * s;
    }
#pragma unroll
    for (int off = 16; off > 0; off >>= 1) {
        ac += __shfl_down_sync(0xffffffff, ac, off);
        as += __shfl_down_sync(0xffffffff, as, off);
    }
    int lane = threadIdx.x & 31, w = threadIdx.x >> 5;
    if (lane == 0) { wc[w] = ac; ws[w] = as; }
    __syncthreads();
    if (threadIdx.x == 0) {
        float sc = 0.f, ss = 0.f;
#pragma unroll
        for (int u = 0; u < 8; u++) { sc += wc[u]; ss += ws[u]; }
        float sw = d_sqw[t];
        d_sfw[t]       = sw * sc;
        d_sfw[NKH + t] = sw * ss;
    }
}

// ------- launch 4 (ncu): B partials = PHI^T sfw (116 blocks x 80 rows) ------
__global__ void k_B() {
    int b = blockIdx.x;
    int t0 = b * 80, t1 = t0 + 80;
    int i0 = threadIdx.x;            // atoms i0, i0+256, i0+512, i0+768
    double acc[4] = {0.0, 0.0, 0.0, 0.0};
    for (int t = t0; t < t1; t += 2) {
        float w0 = d_sfw[t], w1 = d_sfw[t+1];
        const float* r0 = &d_PHI[(size_t)t*NMET];
        const float* r1 = r0 + NMET;
#pragma unroll
        for (int u = 0; u < 4; u++) {
            acc[u] += (double)r0[i0 + u*256] * (double)w0
                    + (double)r1[i0 + u*256] * (double)w1;
        }
    }
#pragma unroll
    for (int u = 0; u < 4; u++) d_Bp[b][i0 + u*256] = acc[u];
}

// tri decode: L -> (bi, bj) with bi >= bj
static __device__ __forceinline__ void tri_decode(int L, int* bi, int* bj) {
    int bt = (int)((sqrtf(8.f*L + 1.f) - 1.f) * 0.5f);
    while ((bt+1)*(bt+2)/2 <= L) bt++;
    while (bt*(bt+1)/2 > L) bt--;
    *bi = bt;
    *bj = L - bt*(bt+1)/2;
}

// -------- launch 5: A = PHI^T PHI lower-tri, split-K=2 ----------------------
__global__ __launch_bounds__(256) void k_gemm() {
    __shared__ float As[2][16][64];
    __shared__ float Bs[2][16][64];
    int L = blockIdx.x % NTILE;
    int h = blockIdx.x / NTILE;
    int bi, bj;
    tri_decode(L, &bi, &bj);
    bi *= 64; bj *= 64;
    int k0 = h * KHALF;
    int tid = threadIdx.x;
    int lr = tid >> 4, lc = (tid & 15) * 4;

    *(float4*)&As[0][lr][lc] = *(const float4*)&d_PHI[(size_t)(k0+lr)*NMET + bi + lc];
    *(float4*)&Bs[0][lr][lc] = *(const float4*)&d_PHI[(size_t)(k0+lr)*NMET + bj + lc];
    __syncthreads();

    int ty = tid >> 4, tx = tid & 15;
    float acc[4][4] = {};
    int buf = 0;
    for (int t0 = k0; t0 < k0 + KHALF; t0 += 16) {
        float4 fa, fb;
        bool more = (t0 + 16 < k0 + KHALF);
        if (more) {
            fa = *(const float4*)&d_PHI[(size_t)(t0+16+lr)*NMET + bi + lc];
            fb = *(const float4*)&d_PHI[(size_t)(t0+16+lr)*NMET + bj + lc];
        }
#pragma unroll
        for (int kk = 0; kk < 16; kk++) {
            float4 a4 = *(const float4*)&As[buf][kk][ty*4];
            float4 b4 = *(const float4*)&Bs[buf][kk][tx*4];
            float a[4] = {a4.x, a4.y, a4.z, a4.w};
            float b[4] = {b4.x, b4.y, b4.z, b4.w};
#pragma unroll
            for (int u = 0; u < 4; u++)
#pragma unroll
                for (int v = 0; v < 4; v++) acc[u][v] += a[u] * b[v];
        }
        if (more) {
            __syncthreads();
            *(float4*)&As[buf^1][lr][lc] = fa;
            *(float4*)&Bs[buf^1][lr][lc] = fb;
            __syncthreads();
            buf ^= 1;
        }
    }
    float* dst = &d_Ap[h][(size_t)L * 4096];
#pragma unroll
    for (int u = 0; u < 4; u++)
        *(float4*)&dst[(ty*4+u)*64 + tx*4] =
            make_float4(acc[u][0], acc[u][1], acc[u][2], acc[u][3]);
}

// -------- launch 6: combine split-K partials + mirror -----------------------
__global__ void k_comb() {
    int idx = blockIdx.x * 256 + threadIdx.x;   // NTILE*4096 total
    int t = idx >> 12, e = idx & 4095;
    int bi, bj;
    tri_decode(t, &bi, &bj);
    int row = bi*64 + (e >> 6), col = bj*64 + (e & 63);
    float v = d_Ap[0][idx] + d_Ap[1][idx];
    d_A[row*NMET + col] = v;
    d_Afull[row*NMET + col] = v;
    if (bi != bj) {
        d_A[col*NMET + row] = v;
        d_Afull[col*NMET + row] = v;
    }
}

// ---------------- Cholesky building blocks (launch-synchronized) ------------
// factor 64x64 lower block in smem (stride 65); write L + L^T + inv diag
__device__ void potf_smem(float* sm, float* pinv, int o) {
    int tid = threadIdx.x;
    for (int j = 0; j < 64; j++) {
        if (tid == 0) {
            float s = sqrtf(sm[j*65+j]);
            sm[j*65+j] = s;
            *pinv = 1.0f / s;
        }
        __syncthreads();
        float inv = *pinv;
        for (int i2 = j + 1 + tid; i2 < 64; i2 += 256) sm[i2*65+j] *= inv;
        __syncthreads();
        for (int l = tid; l < 4096; l += 256) {
            int r = l >> 6, c = l & 63;
            if (r > j && c > j && c <= r) sm[r*65+c] -= sm[r*65+j] * sm[c*65+j];
        }
        __syncthreads();
    }
    for (int l = tid; l < 4096; l += 256) {
        int r = l >> 6, c = l & 63;
        float v = (c <= r) ? sm[r*65+c] : 0.0f;
        d_A[(o+r)*NMET + o + c] = v;
        d_LT[(o+c)*NMET + o + r] = v;
    }
    if (tid < 64) d_invf[o+tid] = 1.0f / sm[tid*65+tid];
    __syncthreads();
}

// global float4 load -> scalar smem scatter (smem stride 65 not 16B aligned)
static __device__ __forceinline__ void ld_tile64(float* sm, const float* g, int ldg) {
    int tid = threadIdx.x;
    for (int l = tid; l < 1024; l += 256) {
        int r = l >> 4, c4 = (l & 15) * 4;
        float4 f = *(const float4*)&g[r*ldg + c4];
        sm[r*65 + c4 + 0] = f.x;
        sm[r*65 + c4 + 1] = f.y;
        sm[r*65 + c4 + 2] = f.z;
        sm[r*65 + c4 + 3] = f.w;
    }
}

// standalone potf for panel 0
__global__ __launch_bounds__(256) void k_potf0() {
    __shared__ float sA[64*65];
    __shared__ float sInv;
    ld_tile64(sA, &d_A[0], NMET);
    __syncthreads();
    potf_smem(sA, &sInv, 0);
}

// trsm for panel p: rows below diag, smem-staged, coalesced IO
__global__ __launch_bounds__(256) void k_trsm(int p) {
    __shared__ float sA[64*65];
    __shared__ float sB[ROWS_T*65];
    __shared__ float sDi[64];
    int tid = threadIdx.x;
    int o = p * NB, s = o + NB;
    int m = NMET - s;
    int r0 = blockIdx.x * ROWS_T;
    if (r0 >= m) return;
    int nrows = m - r0; if (nrows > ROWS_T) nrows = ROWS_T;
    ld_tile64(sA, &d_A[o*NMET + o], NMET);         // diag block
    for (int l = tid; l < nrows * 16; l += 256) {  // panel rows
        int r = l >> 4, c4 = (l & 15) * 4;
        float4 f = *(const float4*)&d_A[(s + r0 + r)*NMET + o + c4];
        sB[r*65 + c4 + 0] = f.x;
        sB[r*65 + c4 + 1] = f.y;
        sB[r*65 + c4 + 2] = f.z;
        sB[r*65 + c4 + 3] = f.w;
    }
    __syncthreads();
    if (tid < 64) sDi[tid] = 1.0f / sA[tid*65+tid];
    __syncthreads();
    if (tid < nrows) {
        float* P = &sB[tid*65];
#pragma unroll 1
        for (int j = 0; j < 64; j++) {
            float v = P[j];
            for (int mm = 0; mm < j; mm++) v -= P[mm] * sA[j*65+mm];
            P[j] = v * sDi[j];
        }
    }
    __syncthreads();
    for (int l = tid; l < nrows * 64; l += 256) {
        int r = l >> 6, c = l & 63;
        d_A[(s + r0 + r)*NMET + o + c] = sB[r*65 + c];
    }
    for (int l = tid; l < nrows * 64; l += 256) {
        int c = l / nrows, r = l % nrows;
        d_LT[(o + c)*NMET + s + r0 + r] = sB[r*65 + c];
    }
}

// syrk trailing update for panel p; tile 0 (next diag) fuses potf(p+1)
__global__ __launch_bounds__(256) void k_syrk(int p) {
    __shared__ float sA[64*65];
    __shared__ float sB[64*65];
    __shared__ float sInv;
    int tid = threadIdx.x;
    int o = p * NB, s = o + NB;
    int I, J;
    tri_decode(blockIdx.x, &I, &J);
    int rI = s + I*NB, rJ = s + J*NB;
    ld_tile64(sA, &d_A[rI*NMET + o], NMET);
    ld_tile64(sB, &d_A[rJ*NMET + o], NMET);
    __syncthreads();
    int ty = tid >> 4, tx = tid & 15;
    float acc[4][4] = {};
#pragma unroll
    for (int k = 0; k < 64; k++) {
        float a[4], b[4];
#pragma unroll
        for (int u = 0; u < 4; u++) {
            a[u] = sA[(ty*4+u)*65 + k];
            b[u] = sB[(tx*4+u)*65 + k];
        }
#pragma unroll
        for (int u = 0; u < 4; u++)
#pragma unroll
            for (int v = 0; v < 4; v++) acc[u][v] += a[u] * b[v];
    }
    __syncthreads();
    if (blockIdx.x == 0) {        // next diag tile: update in smem + factor
#pragma unroll
        for (int u = 0; u < 4; u++)
#pragma unroll
            for (int v = 0; v < 4; v++)
                sA[(ty*4+u)*65 + tx*4+v] =
                    d_A[(rI+ty*4+u)*NMET + rJ + tx*4+v] - acc[u][v];
        __syncthreads();
        potf_smem(sA, &sInv, rI);
    } else {
#pragma unroll
        for (int u = 0; u < 4; u++)
#pragma unroll
            for (int v = 0; v < 4; v++)
                d_A[(rI+ty*4+u)*NMET + rJ + tx*4+v] -= acc[u][v];
    }
}

// ------- dual-RHS fp32 triangular solves (refine uses fp64 residual) --------
// refine==0: reduce d_Bp -> d_B, solve;  refine==1: solve residual + output
__global__ __launch_bounds__(1024) void k_trsv(int refine,
                                               const float* __restrict__ q,
                                               float* __restrict__ out) {
    __shared__ float y1[NMET], y2[NMET];
    __shared__ double z1[NMET], z2[NMET];
    __shared__ double lam_s;
    int i = threadIdx.x, lane = i & 31, warp = i >> 5;
    if (refine) {
        y1[i] = (float)d_r1[i]; y2[i] = (float)d_r2[i];
    } else {
        double s = 0.0;
        for (int k = 0; k < NBB; k++) s += d_Bp[k][i];
        double bv = -s;
        d_B[i] = bv;
        y1[i] = (float)bv; y2[i] = 1.0f;
    }
    __syncthreads();

    // forward: L y = b
    for (int jb = 0; jb < NMET; jb += 32) {
        if (warp == 0) {
            float a1 = y1[jb+lane], a2 = y2[jb+lane];
            float di = d_invf[jb+lane];
            float Lr[32];
#pragma unroll
            for (int j4 = 0; j4 < 8; j4++) {
                float4 f = *(const float4*)&d_A[(jb+lane)*NMET + jb + j4*4];
                Lr[j4*4] = f.x; Lr[j4*4+1] = f.y; Lr[j4*4+2] = f.z; Lr[j4*4+3] = f.w;
            }
#pragma unroll
            for (int j = 0; j < 32; j++) {
                float sv = __shfl_sync(0xffffffff, di, j);
                float v1 = __shfl_sync(0xffffffff, a1, j) * sv;
                float v2 = __shfl_sync(0xffffffff, a2, j) * sv;
                if (lane == j) { a1 = v1; a2 = v2; }
                else if (lane > j) {
                    a1 -= Lr[j] * v1; a2 -= Lr[j] * v2;
                }
            }
            y1[jb+lane] = a1; y2[jb+lane] = a2;
        }
        __syncthreads();
        if (i >= jb + 32) {
            float s1 = y1[i], s2 = y2[i];
#pragma unroll
            for (int j = 0; j < 32; j++) {
                float l = d_LT[(jb+j)*NMET + i];
                s1 -= l * y1[jb+j];
                s2 -= l * y2[jb+j];
            }
            y1[i] = s1; y2[i] = s2;
        }
        __syncthreads();
    }

    // backward: L^T x = y
    for (int jb = NMET - 32; jb >= 0; jb -= 32) {
        if (warp == 0) {
            float a1 = y1[jb+lane], a2 = y2[jb+lane];
            float di = d_invf[jb+lane];
            float Lr[32];     // Lr[j] = L^T[jb+lane][jb+j] = L[jb+j][jb+lane]
#pragma unroll
            for (int j4 = 0; j4 < 8; j4++) {
                float4 f = *(const float4*)&d_LT[(jb+lane)*NMET + jb + j4*4];
                Lr[j4*4] = f.x; Lr[j4*4+1] = f.y; Lr[j4*4+2] = f.z; Lr[j4*4+3] = f.w;
            }
#pragma unroll
            for (int j = 31; j >= 0; j--) {
                float sv = __shfl_sync(0xffffffff, di, j);
                float v1 = __shfl_sync(0xffffffff, a1, j) * sv;
                float v2 = __shfl_sync(0xffffffff, a2, j) * sv;
                if (lane == j) { a1 = v1; a2 = v2; }
                else if (lane < j) {
                    a1 -= Lr[j] * v1; a2 -= Lr[j] * v2;
                }
            }
            y1[jb+lane] = a1; y2[jb+lane] = a2;
        }
        __syncthreads();
        if (i < jb) {
            float s1 = y1[i], s2 = y2[i];
#pragma unroll
            for (int j = 0; j < 32; j++) {
                float l = d_A[(jb+j)*NMET + i];   // L rows: coalesced
                s1 -= l * y1[jb+j];
                s2 -= l * y2[jb+j];
            }
            y1[i] = s1; y2[i] = s2;
        }
        __syncthreads();
    }

    double xf1, xf2;
    if (refine) { xf1 = d_x1[i] + (double)y1[i]; xf2 = d_x2[i] + (double)y2[i]; }
    else        { xf1 = (double)y1[i];           xf2 = (double)y2[i]; }
    d_x1[i] = xf1; d_x2[i] = xf2;
    z1[i] = xf1; z2[i] = xf2;
    __syncthreads();
    for (int off = 512; off > 0; off >>= 1) {
        if (i < off) { z1[i] += z1[i+off]; z2[i] += z2[i+off]; }
        __syncthreads();
    }
    if (i == 0) { lam_s = z1[0] / z2[0]; d_lam = lam_s; }
    __syncthreads();
    if (refine) {                    // fused output splice
        double lam = lam_s;
        out[i] = (float)(xf1 - lam * xf2);
        for (int j = NMET + i; j < NATOM; j += NMET) out[j] = q[j];
    }
}

// ---------------- residual r = b - A x (fp64 accumulate) --------------------
__global__ void k_resid() {
    int lane = threadIdx.x & 31, wr = threadIdx.x >> 5;
    int row = blockIdx.x * 8 + wr;
    double a1 = 0.0, a2 = 0.0;
    for (int j = lane; j < NMET; j += 32) {
        double a = (double)d_Afull[row*NMET + j];
        a1 += a * d_x1[j];
        a2 += a * d_x2[j];
    }
    for (int off = 16; off > 0; off >>= 1) {
        a1 += __shfl_down_sync(0xffffffff, a1, off);
        a2 += __shfl_down_sync(0xffffffff, a2, off);
    }
    if (lane == 0) {
        d_r1[row] = d_B[row] - a1;
        d_r2[row] = 1.0 - a2;
    }
}

// ------------------------------ launch --------------------------------------
extern "C" void kernel_launch(void* const* d_in, const int* in_sizes, int n_in,
                              void* d_out, int out_size) {
    const float* pos  = (const float*)d_in[0];
    const float* q    = (const float*)d_in[1];
    const float* cell = (const float*)d_in[2];
    float* out = (float*)d_out;

    k_prep<<<80, 256>>>(pos, cell);                 // 1
    k_phi<<<NKH, 256>>>();                          // 2
    k_sf<<<NKH, 256>>>(q);                          // 3
    k_B<<<NBB, 256>>>();                            // 4  <- ncu captures this
    k_gemm<<<2 * NTILE, 256>>>();                   // 5
    k_comb<<<NTILE * 4096 / 256, 256>>>();          // 6
    k_potf0<<<1, 256>>>();
    for (int p = 0; p < NPAN - 1; p++) {
        int m = NMET - (p + 1) * NB;
        int nt = m / NB;
        k_trsm<<<(m + ROWS_T - 1) / ROWS_T, 256>>>(p);
        k_syrk<<<nt * (nt + 1) / 2, 256>>>(p);      // tile 0 fuses potf(p+1)
    }
    k_trsv<<<1, 1024>>>(0, q, out);
    k_resid<<<128, 256>>>();
    k_trsv<<<1, 1024>>>(1, q, out);
}